// round 8
// baseline (speedup 1.0000x reference)
#include <cuda_runtime.h>
#include <cuda_bf16.h>

#define LN_EPS 1e-5f

// 4-level butterfly: after this, lanes 0 and 16 each hold the full 32-lane sum
// only if we do 5 levels; with 4 levels (o=8..1), each 16-lane half is reduced,
// i.e. lane 0 holds sum of lanes 0..15, lane 16 holds sum of lanes 16..31.
static __device__ __forceinline__ float half_warp_sum(float v) {
#pragma unroll
    for (int o = 8; o; o >>= 1) v += __shfl_xor_sync(0xffffffffu, v, o);
    return v;
}

// One BLOCK (192 threads = 6 warps) per output row (b, t).
// H=768 -> 192 float4 -> exactly ONE float4 per lane per stream.
// All 7 global streams front-batched so only FMA+STG remain after the barrier.
// Reduction: 4 shuffle levels -> 12 half-warp partials in smem -> broadcast sum.
__global__ void __launch_bounds__(192, 8)
prev_embedding_kernel(
    const float* __restrict__ cv,    // [V, H]
    const float* __restrict__ ocr,   // [B, N, H]
    const int*   __restrict__ ids,   // [B, T]
    const float* __restrict__ cvg, const float* __restrict__ cvb,
    const float* __restrict__ og,  const float* __restrict__ ob,
    const float* __restrict__ pos,   // [T, H]
    const float* __restrict__ typ,   // [2, H]
    const float* __restrict__ eg,  const float* __restrict__ eb,
    float* __restrict__ out,         // [B, T, H]
    int V, int N, int T, int H)
{
    const int t  = blockIdx.x;
    const int b  = blockIdx.y;
    const int bt = b * T + t;
    const int l  = threadIdx.x;          // 0..191

    const int id = __ldg(ids + bt);
    const float* src;
    const float* gam;
    const float* bet;
    if (id >= V) {
        int oi = id - V;
        oi = max(0, min(oi, N - 1));
        src = ocr + ((size_t)b * (size_t)N + (size_t)oi) * (size_t)H;
        gam = og; bet = ob;
    } else {
        int ci = max(0, min(id, V - 1));
        src = cv + (size_t)ci * (size_t)H;
        gam = cvg; bet = cvb;
    }

    // ---- front-batched loads: all 7 streams issued before any consumer ----
    const float4 a   = ((const float4*)src)[l];
    const float4 pp  = ((const float4*)(pos + (size_t)t * (size_t)H))[l];
    const float4 tt  = ((const float4*)(typ + ((t >= V) ? (size_t)H : (size_t)0)))[l];
    const float4 g4  = ((const float4*)gam)[l];
    const float4 b4  = ((const float4*)bet)[l];
    const float4 eg4 = ((const float4*)eg)[l];
    const float4 eb4 = ((const float4*)eb)[l];

    const float4 p = make_float4(pp.x + tt.x, pp.y + tt.y, pp.z + tt.z, pp.w + tt.w);

    float sa  = a.x + a.y + a.z + a.w;
    float ssa = a.x * a.x + a.y * a.y + a.z * a.z + a.w * a.w;
    float sp  = p.x + p.y + p.z + p.w;
    float ssp = p.x * p.x + p.y * p.y + p.z * p.z + p.w * p.w;

    // 4 shuffle levels per accumulator (independent chains, pipelined).
    sa = half_warp_sum(sa); ssa = half_warp_sum(ssa);
    sp = half_warp_sum(sp); ssp = half_warp_sum(ssp);

    // 12 half-warp partials: lanes 0 and 16 of each of the 6 warps.
    __shared__ float4 red[12];
    const int hw = l >> 4;               // half-warp index 0..11
    if ((l & 15) == 0) red[hw] = make_float4(sa, ssa, sp, ssp);
    __syncthreads();

    float4 acc = red[0];
#pragma unroll
    for (int i = 1; i < 12; i++) {
        float4 ri = red[i];
        acc.x += ri.x; acc.y += ri.y; acc.z += ri.z; acc.w += ri.w;
    }
    sa = acc.x; ssa = acc.y; sp = acc.z; ssp = acc.w;

    const float invH = 1.0f / (float)H;
    const float mua = sa * invH;
    const float va  = fmaf(-mua, mua, ssa * invH);
    const float mup = sp * invH;
    const float vp  = fmaf(-mup, mup, ssp * invH);
    const float ra  = rsqrtf(va + LN_EPS);
    const float rp  = rsqrtf(vp + LN_EPS);

    // ---- pure-FMA epilogue (all operands already in registers) ----
    float4 r;
    r.x = (a.x - mua) * ra * g4.x + b4.x + (p.x - mup) * rp * eg4.x + eb4.x;
    r.y = (a.y - mua) * ra * g4.y + b4.y + (p.y - mup) * rp * eg4.y + eb4.y;
    r.z = (a.z - mua) * ra * g4.z + b4.z + (p.z - mup) * rp * eg4.z + eb4.z;
    r.w = (a.w - mua) * ra * g4.w + b4.w + (p.w - mup) * rp * eg4.w + eb4.w;
    ((float4*)(out + (size_t)bt * (size_t)H))[l] = r;
}

extern "C" void kernel_launch(void* const* d_in, const int* in_sizes, int n_in,
                              void* d_out, int out_size) {
    const float* cv  = (const float*)d_in[0];
    const float* ocr = (const float*)d_in[1];
    const int*   ids = (const int*)d_in[2];
    const float* cvg = (const float*)d_in[3];
    const float* cvb = (const float*)d_in[4];
    const float* og  = (const float*)d_in[5];
    const float* ob  = (const float*)d_in[6];
    const float* pos = (const float*)d_in[7];
    const float* typ = (const float*)d_in[8];
    const float* eg  = (const float*)d_in[9];
    const float* eb  = (const float*)d_in[10];
    float* out = (float*)d_out;

    const int H  = in_sizes[3];
    const int V  = in_sizes[0] / H;
    const int T  = in_sizes[7] / H;
    const int BT = in_sizes[2];       // B * T
    const int B  = BT / T;
    const int N  = in_sizes[1] / (B * H);

    dim3 grid(T, B);
    prev_embedding_kernel<<<grid, H / 4>>>(
        cv, ocr, ids, cvg, cvb, og, ob, pos, typ, eg, eb, out, V, N, T, H);
}